// round 9
// baseline (speedup 1.0000x reference)
#include <cuda_runtime.h>

// Fixed shape: [B=2, D=128, H=160, W=192, C=3] float32 fields.
#define DD 128
#define HH 160
#define WW 192
#define NB 2
#define DHW (DD * HH * WW)          // 3,932,160 voxels per batch
#define TOTAL (NB * DHW)            // 7,864,320 voxels
#define QSCALE 1024.0f
#define QINV   (1.0f / 1024.0f)
#define QBLOCKS (TOTAL / 1024)      // 7680 quant blocks per tensor

// Z-paired quantized gather volumes: per voxel a 16B record with int16
// fixed-point values of this voxel AND its z+1 neighbor (clamped at row end).
__device__ uint4 g_t1p[TOTAL];
__device__ uint4 g_t2p[TOTAL];
__device__ int g_cnt;
__device__ volatile int g_flag;

struct f3 { float x, y, z; };

__device__ __forceinline__ unsigned pk(float lo, float hi) {
    int il = __float2int_rn(lo * QSCALE);
    int ih = __float2int_rn(hi * QSCALE);
    return (unsigned)(il & 0xFFFF) | ((unsigned)ih << 16);
}
__device__ __forceinline__ float sxlo(unsigned u) { return (float)((int)(u << 16) >> 16); }
__device__ __forceinline__ float sxhi(unsigned u) { return (float)((int)u >> 16); }

// ---------------------------------------------------------------------------
// Quant block: 1024 voxels AoS3 fp32 -> z-paired int16 records, smem-staged
// coalesced stores.
// ---------------------------------------------------------------------------
__device__ __forceinline__ void quant_block(const float4* __restrict__ src,
                                            uint4* __restrict__ dst,
                                            int bid, int tx, uint4* st) {
    int g = bid * 256 + tx;              // voxel-group of 4

    float4 a = __ldg(src + g * 3 + 0);   // v0.xyz v1.x
    float4 b = __ldg(src + g * 3 + 1);   // v1.yz  v2.xy
    float4 c = __ldg(src + g * 3 + 2);   // v2.z   v3.xyz

    int w0 = (g % (WW / 4)) * 4;
    float nx, ny, nz;
    if (w0 + 4 < WW) {
        float4 d = __ldg(src + g * 3 + 3);
        nx = d.x; ny = d.y; nz = d.z;
    } else {
        nx = c.y; ny = c.z; nz = c.w;
    }

    float vx[5] = {a.x, a.w, b.z, c.y, nx};
    float vy[5] = {a.y, b.x, b.w, c.z, ny};
    float vz[5] = {a.z, b.y, c.x, c.w, nz};

#pragma unroll
    for (int i = 0; i < 4; i++) {
        uint4 u;
        u.x = pk(vx[i], vy[i]);
        u.y = pk(vz[i], vx[i + 1]);
        u.z = pk(vy[i + 1], vz[i + 1]);
        u.w = 0u;
        st[tx * 4 + i] = u;
    }
    __syncthreads();

    size_t ob = (size_t)bid * 1024;
#pragma unroll
    for (int i = 0; i < 4; i++) {
        int k = tx + i * 256;
        dst[ob + k] = st[k];
    }
}

// ---------------------------------------------------------------------------
// Coord/gather helpers for z-paired records.
// ---------------------------------------------------------------------------
struct Coord {
    int r00, r01, r10, r11;
    float w00, w01, w10, w11;
    float wz0q, wz1q;
};

__device__ __forceinline__ Coord make_coord(float fx, float fy, float fz) {
    fx = fminf(fmaxf(fx, 0.f), (float)(DD - 1));
    fy = fminf(fmaxf(fy, 0.f), (float)(HH - 1));
    fz = fminf(fmaxf(fz, 0.f), (float)(WW - 1));
    float x0f = floorf(fx), y0f = floorf(fy), z0f = floorf(fz);
    int x0 = (int)x0f, y0 = (int)y0f, z0 = (int)z0f;
    int x1 = min(x0 + 1, DD - 1);
    int y1 = min(y0 + 1, HH - 1);
    float wx1 = fx - x0f, wy1 = fy - y0f, wz1 = fz - z0f;
    float wx0 = 1.f - wx1, wy0 = 1.f - wy1, wz0 = 1.f - wz1;
    Coord c;
    c.r00 = (x0 * HH + y0) * WW + z0;
    c.r01 = (x0 * HH + y1) * WW + z0;
    c.r10 = (x1 * HH + y0) * WW + z0;
    c.r11 = (x1 * HH + y1) * WW + z0;
    c.w00 = wx0 * wy0; c.w01 = wx0 * wy1;
    c.w10 = wx1 * wy0; c.w11 = wx1 * wy1;
    c.wz0q = wz0 * QINV; c.wz1q = wz1 * QINV;
    return c;
}

__device__ __forceinline__ f3 gather_trilerp(const uint4* __restrict__ v,
                                             const Coord& c) {
    uint4 u00 = __ldg(v + c.r00);
    uint4 u01 = __ldg(v + c.r01);
    uint4 u10 = __ldg(v + c.r10);
    uint4 u11 = __ldg(v + c.r11);
    f3 r;
    r.x = c.w00 * fmaf(c.wz0q, sxlo(u00.x), c.wz1q * sxhi(u00.y))
        + c.w01 * fmaf(c.wz0q, sxlo(u01.x), c.wz1q * sxhi(u01.y))
        + c.w10 * fmaf(c.wz0q, sxlo(u10.x), c.wz1q * sxhi(u10.y))
        + c.w11 * fmaf(c.wz0q, sxlo(u11.x), c.wz1q * sxhi(u11.y));
    r.y = c.w00 * fmaf(c.wz0q, sxhi(u00.x), c.wz1q * sxlo(u00.z))
        + c.w01 * fmaf(c.wz0q, sxhi(u01.x), c.wz1q * sxlo(u01.z))
        + c.w10 * fmaf(c.wz0q, sxhi(u10.x), c.wz1q * sxlo(u10.z))
        + c.w11 * fmaf(c.wz0q, sxhi(u11.x), c.wz1q * sxlo(u11.z));
    r.z = c.w00 * fmaf(c.wz0q, sxlo(u00.y), c.wz1q * sxhi(u00.z))
        + c.w01 * fmaf(c.wz0q, sxlo(u01.y), c.wz1q * sxhi(u01.z))
        + c.w10 * fmaf(c.wz0q, sxlo(u10.y), c.wz1q * sxhi(u10.z))
        + c.w11 * fmaf(c.wz0q, sxlo(u11.y), c.wz1q * sxhi(u11.z));
    return r;
}

// ---------------------------------------------------------------------------
// Kernel A: quantize t2; block 0 also resets the t1-ready flag/counter.
// ---------------------------------------------------------------------------
__global__ __launch_bounds__(256)
void quant_t2_kernel(const float4* __restrict__ t2, uint4* __restrict__ t2p) {
    __shared__ uint4 st[1024];
    if (blockIdx.x == 0 && threadIdx.x == 0) {
        g_cnt = 0;
        g_flag = 0;
    }
    quant_block(t2, t2p, blockIdx.x, threadIdx.x, st);
}

// ---------------------------------------------------------------------------
// Kernel B: bids [0, QBLOCKS) quantize t1 and signal; the rest run the fused
// compose, spinning on the t1-ready flag between phase-1 and phase-2.
// Quant bids precede compose bids in dispatch order -> no deadlock.
// ---------------------------------------------------------------------------
__global__ __launch_bounds__(256)
void fused_kernel(const float4* __restrict__ t3v,
                  const float4* __restrict__ t1,
                  uint4* __restrict__ t1p,
                  const uint4* __restrict__ t2p,
                  float4* __restrict__ outv) {
    __shared__ float4 sh4[1024];    // 16 KB: quant staging OR compose I/O
    int bid = blockIdx.x;
    int tx = threadIdx.x;

    if (bid < QBLOCKS) {
        quant_block(t1, t1p, bid, tx, (uint4*)sh4);
        __threadfence();
        __syncthreads();
        if (tx == 0) {
            if (atomicAdd(&g_cnt, 1) == QBLOCKS - 1) {
                __threadfence();
                g_flag = 1;
            }
        }
        return;
    }

    // ---- fused compose for 256 voxels ----
    float* s_in = (float*)sh4;
    float* s_out = (float*)sh4 + 768;
    int cbid = bid - QBLOCKS;

    if (tx < 192) ((float4*)s_in)[tx] = __ldg(t3v + (size_t)cbid * 192 + tx);
    __syncthreads();

    int tid = cbid * 256 + tx;
    int w = tid % WW;
    int t = tid / WW;
    int h = t % HH;
    t /= HH;
    int d = t % DD;
    int b = t / DD;

    const uint4* v2 = t2p + (size_t)b * DHW;
    const uint4* v1 = t1p + (size_t)b * DHW;

    float sx = s_in[tx * 3 + 0];
    float sy = s_in[tx * 3 + 1];
    float sz = s_in[tx * 3 + 2];

    // phase-1: c2 = t3 + warp(t2, t3)
    Coord c = make_coord((float)d + sx, (float)h + sy, (float)w + sz);
    f3 g2 = gather_trilerp(v2, c);
    float cx = sx + g2.x;
    float cy = sy + g2.y;
    float cz = sz + g2.z;

    // wait for t1p ready (usually already set)
    if (tx == 0) {
        while (g_flag == 0) { __nanosleep(200); }
    }
    __syncthreads();
    __threadfence();

    // phase-2: out = c2 + warp(t1, c2)
    Coord dch = make_coord((float)d + cx, (float)h + cy, (float)w + cz);
    f3 g1 = gather_trilerp(v1, dch);

    s_out[tx * 3 + 0] = cx + g1.x;
    s_out[tx * 3 + 1] = cy + g1.y;
    s_out[tx * 3 + 2] = cz + g1.z;
    __syncthreads();

    if (tx < 192) outv[(size_t)cbid * 192 + tx] = ((float4*)s_out)[tx];
}

extern "C" void kernel_launch(void* const* d_in, const int* in_sizes, int n_in,
                              void* d_out, int out_size) {
    const float* t1 = (const float*)d_in[0];
    const float* t2 = (const float*)d_in[1];
    const float* t3 = (const float*)d_in[2];
    float* out = (float*)d_out;

    uint4 *t1p, *t2p;
    cudaGetSymbolAddress((void**)&t1p, g_t1p);
    cudaGetSymbolAddress((void**)&t2p, g_t2p);

    quant_t2_kernel<<<QBLOCKS, 256>>>((const float4*)t2, t2p);

    int blocks = QBLOCKS + TOTAL / 256;    // 7680 quant + 30720 compose
    fused_kernel<<<blocks, 256>>>((const float4*)t3, (const float4*)t1,
                                  t1p, t2p, (float4*)out);
}

// round 10
// speedup vs baseline: 1.2178x; 1.2178x over previous
#include <cuda_runtime.h>

// Fixed shape: [B=2, D=128, H=160, W=192, C=3] float32 fields.
#define DD 128
#define HH 160
#define WW 192
#define NB 2
#define DHW (DD * HH * WW)          // 3,932,160 voxels per batch
#define TOTAL (NB * DHW)            // 7,864,320 voxels
#define QSCALE 1024.0f
#define QINV   (1.0f / 1024.0f)

// Z-paired quantized gather volumes: per voxel a 16B record holding int16
// fixed-point values of this voxel AND its z+1 neighbor (clamped at row end).
//   U.x = pk(lo.x, lo.y)  U.y = pk(lo.z, hi.x)  U.z = pk(hi.y, hi.z)  U.w = 0
__device__ uint4 g_t1p[TOTAL];
__device__ uint4 g_t2p[TOTAL];

struct f3 { float x, y, z; };

__device__ __forceinline__ unsigned pk(float lo, float hi) {
    int il = __float2int_rn(lo * QSCALE);
    int ih = __float2int_rn(hi * QSCALE);
    return (unsigned)(il & 0xFFFF) | ((unsigned)ih << 16);
}
__device__ __forceinline__ float sxlo(unsigned u) { return (float)((int)(u << 16) >> 16); }
__device__ __forceinline__ float sxhi(unsigned u) { return (float)((int)u >> 16); }

// ---------------------------------------------------------------------------
// Merged quant for t1+t2 (grid.y selects tensor). Each thread packs 4 voxels;
// records staged in smem and written warp-coalesced (1024 uint4 per block).
// ---------------------------------------------------------------------------
__global__ __launch_bounds__(256)
void pairquant2_kernel(const float4* __restrict__ t1,
                       const float4* __restrict__ t2,
                       uint4* __restrict__ d1,
                       uint4* __restrict__ d2) {
    __shared__ uint4 st[1024];

    const float4* __restrict__ src = blockIdx.y ? t2 : t1;
    uint4* __restrict__ dst = blockIdx.y ? d2 : d1;

    int g = blockIdx.x * 256 + threadIdx.x;        // voxel-group of 4

    float4 a = __ldg(src + g * 3 + 0);   // v0.xyz v1.x
    float4 b = __ldg(src + g * 3 + 1);   // v1.yz  v2.xy
    float4 c = __ldg(src + g * 3 + 2);   // v2.z   v3.xyz

    int w0 = (g % (WW / 4)) * 4;         // w coord of first voxel in group
    float nx, ny, nz;                    // voxel v4 (w0+4) or clamp to v3
    if (w0 + 4 < WW) {
        float4 d = __ldg(src + g * 3 + 3);
        nx = d.x; ny = d.y; nz = d.z;
    } else {
        nx = c.y; ny = c.z; nz = c.w;
    }

    float vx[5] = {a.x, a.w, b.z, c.y, nx};
    float vy[5] = {a.y, b.x, b.w, c.z, ny};
    float vz[5] = {a.z, b.y, c.x, c.w, nz};

#pragma unroll
    for (int i = 0; i < 4; i++) {
        uint4 u;
        u.x = pk(vx[i], vy[i]);
        u.y = pk(vz[i], vx[i + 1]);
        u.z = pk(vy[i + 1], vz[i + 1]);
        u.w = 0u;
        st[threadIdx.x * 4 + i] = u;
    }
    __syncthreads();

    size_t out_base = (size_t)blockIdx.x * 1024;
#pragma unroll
    for (int i = 0; i < 4; i++) {
        int k = threadIdx.x + i * 256;
        dst[out_base + k] = st[k];
    }
}

// ---------------------------------------------------------------------------
// Trilinear interp from z-paired volume: 4 aligned LDG.128, each delivering
// both z-corners of one (x,y) row.
// ---------------------------------------------------------------------------
__device__ __forceinline__ f3 trilerp_p(const uint4* __restrict__ v,
                                        float fx, float fy, float fz) {
    fx = fminf(fmaxf(fx, 0.f), (float)(DD - 1));
    fy = fminf(fmaxf(fy, 0.f), (float)(HH - 1));
    fz = fminf(fmaxf(fz, 0.f), (float)(WW - 1));
    float x0f = floorf(fx), y0f = floorf(fy), z0f = floorf(fz);
    int x0 = (int)x0f, y0 = (int)y0f, z0 = (int)z0f;
    int x1 = min(x0 + 1, DD - 1);
    int y1 = min(y0 + 1, HH - 1);
    float wx1 = fx - x0f, wy1 = fy - y0f, wz1 = fz - z0f;
    float wx0 = 1.f - wx1, wy0 = 1.f - wy1, wz0 = 1.f - wz1;

    uint4 u00 = __ldg(v + (x0 * HH + y0) * WW + z0);
    uint4 u01 = __ldg(v + (x0 * HH + y1) * WW + z0);
    uint4 u10 = __ldg(v + (x1 * HH + y0) * WW + z0);
    uint4 u11 = __ldg(v + (x1 * HH + y1) * WW + z0);

    float w00 = wx0 * wy0, w01 = wx0 * wy1;
    float w10 = wx1 * wy0, w11 = wx1 * wy1;
    float wz0q = wz0 * QINV, wz1q = wz1 * QINV;   // fold dequant into z-weights

    f3 r;
    r.x = w00 * fmaf(wz0q, sxlo(u00.x), wz1q * sxhi(u00.y))
        + w01 * fmaf(wz0q, sxlo(u01.x), wz1q * sxhi(u01.y))
        + w10 * fmaf(wz0q, sxlo(u10.x), wz1q * sxhi(u10.y))
        + w11 * fmaf(wz0q, sxlo(u11.x), wz1q * sxhi(u11.y));
    r.y = w00 * fmaf(wz0q, sxhi(u00.x), wz1q * sxlo(u00.z))
        + w01 * fmaf(wz0q, sxhi(u01.x), wz1q * sxlo(u01.z))
        + w10 * fmaf(wz0q, sxhi(u10.x), wz1q * sxlo(u10.z))
        + w11 * fmaf(wz0q, sxhi(u11.x), wz1q * sxlo(u11.z));
    r.z = w00 * fmaf(wz0q, sxlo(u00.y), wz1q * sxhi(u00.z))
        + w01 * fmaf(wz0q, sxlo(u01.y), wz1q * sxhi(u01.z))
        + w10 * fmaf(wz0q, sxlo(u10.y), wz1q * sxhi(u10.z))
        + w11 * fmaf(wz0q, sxlo(u11.y), wz1q * sxhi(u11.z));
    return r;
}

// ---------------------------------------------------------------------------
// Fused compose (R4 structure: direct scalar coherent I/O, no smem staging),
// with min-blocks hint to push occupancy to 8 blocks/SM (regs <= 32).
// ---------------------------------------------------------------------------
__global__ __launch_bounds__(256, 8)
void compose_kernel(const float* __restrict__ t3,
                    const uint4* __restrict__ t1p,
                    const uint4* __restrict__ t2p,
                    float* __restrict__ out) {
    int tid = blockIdx.x * blockDim.x + threadIdx.x;

    int w = tid % WW;
    int t = tid / WW;
    int h = t % HH;
    t /= HH;
    int d = t % DD;
    int b = t / DD;

    const uint4* v1 = t1p + (size_t)b * DHW;
    const uint4* v2 = t2p + (size_t)b * DHW;

    size_t i3 = (size_t)tid * 3;
    float sx = t3[i3 + 0];
    float sy = t3[i3 + 1];
    float sz = t3[i3 + 2];

    f3 g2 = trilerp_p(v2, (float)d + sx, (float)h + sy, (float)w + sz);
    float cx = sx + g2.x;
    float cy = sy + g2.y;
    float cz = sz + g2.z;

    f3 g1 = trilerp_p(v1, (float)d + cx, (float)h + cy, (float)w + cz);

    out[i3 + 0] = cx + g1.x;
    out[i3 + 1] = cy + g1.y;
    out[i3 + 2] = cz + g1.z;
}

extern "C" void kernel_launch(void* const* d_in, const int* in_sizes, int n_in,
                              void* d_out, int out_size) {
    const float* t1 = (const float*)d_in[0];
    const float* t2 = (const float*)d_in[1];
    const float* t3 = (const float*)d_in[2];
    float* out = (float*)d_out;

    uint4 *t1p, *t2p;
    cudaGetSymbolAddress((void**)&t1p, g_t1p);
    cudaGetSymbolAddress((void**)&t2p, g_t2p);

    dim3 qgrid(TOTAL / 1024, 2);
    pairquant2_kernel<<<qgrid, 256>>>((const float4*)t1, (const float4*)t2,
                                      t1p, t2p);

    compose_kernel<<<TOTAL / 256, 256>>>(t3, t1p, t2p, out);
}